// round 3
// baseline (speedup 1.0000x reference)
#include <cuda_runtime.h>
#include <cuda_bf16.h>

#define N_NODES 100000
#define N_EDGES 1600000
#define HID 128

typedef unsigned long long u64t;

// ---------------- scratch (static device globals; no runtime alloc) ----------
__device__ __align__(16) float g_buf0[(size_t)N_NODES * HID]; // GEMM out (xt)
__device__ __align__(16) float g_buf1[(size_t)N_NODES * HID]; // layer-1 hidden
__device__ float g_dinv[N_NODES];
__device__ int   g_deg[N_NODES];
__device__ int   g_cur[N_NODES];
__device__ int   g_off[N_NODES + 1];
__device__ int   g_src[N_EDGES];
__device__ int   g_is64;          // 1 if edge_index delivered as int64

// ---------------- dtype probe -----------------------------------------------
// int64 nonneg < 2^31: every odd 32-bit word is 0. int32 node ids: essentially
// impossible that 2048 consecutive odd words are all zero.
__global__ void k_probe(const int* __restrict__ ei32) {
    __shared__ int anyNZ;
    if (threadIdx.x == 0) anyNZ = 0;
    __syncthreads();
    int nz = 0;
    #pragma unroll
    for (int i = 0; i < 8; i++) {
        int idx = 2 * (threadIdx.x + 256 * i) + 1;   // odd words 1..4095
        if (ei32[idx] != 0) nz = 1;
    }
    if (nz) atomicOr(&anyNZ, 1);
    __syncthreads();
    if (threadIdx.x == 0) g_is64 = anyNZ ? 0 : 1;
}

__device__ __forceinline__ int edge_at(const void* ei, long long idx) {
    if (g_is64) return (int)((const long long*)ei)[idx];
    return ((const int*)ei)[idx];
}

// ---------------- graph build ------------------------------------------------
__global__ void k_zero() {
    int i = blockIdx.x * blockDim.x + threadIdx.x;
    if (i < N_NODES) { g_deg[i] = 0; g_cur[i] = 0; }
}

__global__ void k_count(const void* __restrict__ ei) {
    int e = blockIdx.x * blockDim.x + threadIdx.x;
    if (e < N_EDGES) {
        int c = edge_at(ei, (long long)N_EDGES + e);   // col (destination)
        if ((unsigned)c < N_NODES) atomicAdd(&g_deg[c], 1);
    }
}

// single-block scan over 100k degrees -> exclusive offsets; dinv = rsqrt(deg+1)
__global__ void k_scan() {
    __shared__ int sh[1024];
    int t = threadIdx.x;
    const int CH = (N_NODES + 1023) / 1024;      // 98
    int start = t * CH;
    int end = start + CH; if (end > N_NODES) end = N_NODES;
    int s = 0;
    for (int i = start; i < end; i++) s += g_deg[i];
    sh[t] = s;
    __syncthreads();
    for (int off = 1; off < 1024; off <<= 1) {
        int v = (t >= off) ? sh[t - off] : 0;
        __syncthreads();
        sh[t] += v;
        __syncthreads();
    }
    int run = sh[t] - s;                          // exclusive base
    for (int i = start; i < end; i++) {
        g_off[i] = run;
        int d = g_deg[i];
        run += d;
        g_dinv[i] = rsqrtf((float)(d + 1));
    }
    if (t == 1023) g_off[N_NODES] = sh[1023];
}

__global__ void k_fill(const void* __restrict__ ei) {
    int e = blockIdx.x * blockDim.x + threadIdx.x;
    if (e < N_EDGES) {
        int r = edge_at(ei, e);
        int c = edge_at(ei, (long long)N_EDGES + e);
        if ((unsigned)r >= N_NODES || (unsigned)c >= N_NODES) return;
        int pos = g_off[c] + atomicAdd(&g_cur[c], 1);
        if ((unsigned)pos < N_EDGES) g_src[pos] = r;
    }
}

// ---------------- GEMM: Y[n,128] = X[n,128] @ W[128,128] --------------------
// 256 threads, 128-row tile, K tiled by 32, 8x8 micro-tile, packed f32x2 FMA.
#define FFMA2(d, a, b) \
    asm("fma.rn.f32x2 %0, %1, %2, %0;" : "+l"(d) : "l"(a), "l"(b))

__global__ void __launch_bounds__(256) k_gemm(const float* __restrict__ Xext,
                                              const float* __restrict__ W,
                                              int srcSel, int dstSel) {
    __shared__ float As[128 * 32];   // [row][k] current K-slab
    __shared__ float Ws[32 * 128];   // [k][col] current K-slab

    const float* X = srcSel ? g_buf1 : Xext;
    float*       Y = dstSel ? g_buf1 : g_buf0;

    int tid = threadIdx.x;
    int rowBase = blockIdx.x * 128;

    int rg = (tid >> 4) << 3;     // row offset (0..120)
    int cg = (tid & 15) << 3;     // col offset (0..120)

    u64t acc[8][4];
    #pragma unroll
    for (int i = 0; i < 8; i++)
        #pragma unroll
        for (int j = 0; j < 4; j++) acc[i][j] = 0ull;

    const float4* Xv = (const float4*)X;
    const float4* Wv = (const float4*)W;

    #pragma unroll 1
    for (int kt = 0; kt < 4; kt++) {
        #pragma unroll
        for (int i = 0; i < 4; i++) {
            int lin = tid + 256 * i;
            int r = lin >> 3;              // 0..127
            int q = lin & 7;
            int gr = rowBase + r;
            float4 v = (gr < N_NODES) ? Xv[(size_t)gr * 32 + kt * 8 + q]
                                      : make_float4(0.f, 0.f, 0.f, 0.f);
            *(float4*)&As[r * 32 + q * 4] = v;
        }
        #pragma unroll
        for (int i = 0; i < 4; i++) {
            int lin = tid + 256 * i;
            int wr = lin >> 5;             // 0..31
            int wc = lin & 31;
            *(float4*)&Ws[wr * 128 + wc * 4] = Wv[(size_t)(kt * 32 + wr) * 32 + wc];
        }
        __syncthreads();

        #pragma unroll
        for (int kk = 0; kk < 32; kk++) {
            u64t b2[4];
            {
                ulonglong2 p0 = *(const ulonglong2*)&Ws[kk * 128 + cg];
                ulonglong2 p1 = *(const ulonglong2*)&Ws[kk * 128 + cg + 4];
                b2[0] = p0.x; b2[1] = p0.y; b2[2] = p1.x; b2[3] = p1.y;
            }
            #pragma unroll
            for (int i = 0; i < 8; i++) {
                float a = As[(rg + i) * 32 + kk];
                u64t a2;
                asm("mov.b64 %0, {%1, %1};" : "=l"(a2) : "f"(a));
                FFMA2(acc[i][0], a2, b2[0]);
                FFMA2(acc[i][1], a2, b2[1]);
                FFMA2(acc[i][2], a2, b2[2]);
                FFMA2(acc[i][3], a2, b2[3]);
            }
        }
        __syncthreads();
    }

    #pragma unroll
    for (int i = 0; i < 8; i++) {
        int r = rowBase + rg + i;
        if (r < N_NODES) {
            ulonglong2* yo = (ulonglong2*)&Y[(size_t)r * 128 + cg];
            ulonglong2 o0; o0.x = acc[i][0]; o0.y = acc[i][1];
            ulonglong2 o1; o1.x = acc[i][2]; o1.y = acc[i][3];
            yo[0] = o0; yo[1] = o1;
        }
    }
}

// ---------------- aggregation: warp-per-node CSC gather ---------------------
// out[c] = dinv[c]^2 * xt[c] + sum_{s in in(c)} dinv[s]*dinv[c]*xt[s] + bias
__global__ void __launch_bounds__(256) k_agg(const float* __restrict__ bias,
                                             float* __restrict__ outExt,
                                             int useExtOut) {
    int gw = (blockIdx.x * blockDim.x + threadIdx.x) >> 5;
    int lane = threadIdx.x & 31;
    if (gw >= N_NODES) return;
    int c = gw;

    const float4* xv = (const float4*)g_buf0;
    float*        out = useExtOut ? outExt : g_buf1;

    float dc = g_dinv[c];
    float4 acc = xv[(size_t)c * 32 + lane];
    float sw = dc * dc;
    acc.x *= sw; acc.y *= sw; acc.z *= sw; acc.w *= sw;

    int e0 = g_off[c], e1 = g_off[c + 1];
    for (int e = e0; e < e1; e++) {
        int s = g_src[e];
        float w = g_dinv[s] * dc;
        float4 v = xv[(size_t)s * 32 + lane];
        acc.x += v.x * w; acc.y += v.y * w; acc.z += v.z * w; acc.w += v.w * w;
    }

    float4 b = ((const float4*)bias)[lane];
    acc.x += b.x; acc.y += b.y; acc.z += b.z; acc.w += b.w;
    ((float4*)out)[(size_t)c * 32 + lane] = acc;
}

// ---------------- launch -----------------------------------------------------
extern "C" void kernel_launch(void* const* d_in, const int* in_sizes, int n_in,
                              void* d_out, int out_size) {
    const float* X  = (const float*)d_in[0];
    const void*  EI = d_in[1];
    const float* W1 = (const float*)d_in[2];
    const float* B1 = (const float*)d_in[3];
    const float* W2 = (const float*)d_in[4];
    const float* B2 = (const float*)d_in[5];
    float*       out = (float*)d_out;

    const int nodeBlocks = (N_NODES + 255) / 256;
    const int edgeBlocks = (N_EDGES + 255) / 256;
    const int gemmBlocks = (N_NODES + 127) / 128;
    const int aggBlocks  = (N_NODES * 32 + 255) / 256;

    // detect edge_index dtype, then build CSC (by destination)
    k_probe<<<1, 256>>>((const int*)EI);
    k_zero<<<nodeBlocks, 256>>>();
    k_count<<<edgeBlocks, 256>>>(EI);
    k_scan<<<1, 1024>>>();
    k_fill<<<edgeBlocks, 256>>>(EI);

    // layer 1
    k_gemm<<<gemmBlocks, 256>>>(X, W1, /*src=*/0, /*dst=*/0);   // xt -> buf0
    k_agg<<<aggBlocks, 256>>>(B1, out, /*useExtOut=*/0);        // h  -> buf1

    // layer 2
    k_gemm<<<gemmBlocks, 256>>>(nullptr, W2, /*src=*/1, /*dst=*/0); // buf1 -> buf0
    k_agg<<<aggBlocks, 256>>>(B2, out, /*useExtOut=*/1);            // -> d_out
}

// round 4
// speedup vs baseline: 1.4532x; 1.4532x over previous
#include <cuda_runtime.h>
#include <cuda_bf16.h>

#define N_NODES 100000
#define N_EDGES 1600000
#define HID 128
#define NBLK ((N_NODES + 255) / 256)   // 391 node blocks

typedef unsigned long long u64t;

// ---------------- scratch (static device globals; no runtime alloc) ----------
__device__ __align__(16) float g_buf0[(size_t)N_NODES * HID]; // GEMM out (xt)
__device__ __align__(16) float g_buf1[(size_t)N_NODES * HID]; // layer-1 hidden
__device__ float g_dinv[N_NODES];
__device__ int   g_deg[N_NODES];
__device__ int   g_cur[N_NODES];
__device__ int   g_off[N_NODES + 1];
__device__ int   g_src[N_EDGES];
__device__ int   g_bsum[NBLK + 1];
__device__ int   g_is64;          // 1 if edge_index delivered as int64

// ---------------- dtype probe -----------------------------------------------
// int64 nonneg < 2^31: every odd 32-bit word is 0. int32 node ids: essentially
// impossible that 2048 consecutive odd words are all zero.
__global__ void k_probe(const int* __restrict__ ei32) {
    __shared__ int anyNZ;
    if (threadIdx.x == 0) anyNZ = 0;
    __syncthreads();
    int nz = 0;
    #pragma unroll
    for (int i = 0; i < 8; i++) {
        int idx = 2 * (threadIdx.x + 256 * i) + 1;   // odd words 1..4095
        if (ei32[idx] != 0) nz = 1;
    }
    if (nz) atomicOr(&anyNZ, 1);
    __syncthreads();
    if (threadIdx.x == 0) g_is64 = anyNZ ? 0 : 1;
}

__device__ __forceinline__ int edge_at(const void* ei, long long idx) {
    if (g_is64) return (int)((const long long*)ei)[idx];
    return ((const int*)ei)[idx];
}

// ---------------- graph build ------------------------------------------------
__global__ void k_zero() {
    int i = blockIdx.x * blockDim.x + threadIdx.x;
    if (i < N_NODES) { g_deg[i] = 0; g_cur[i] = 0; }
}

__global__ void k_count(const void* __restrict__ ei) {
    int e = blockIdx.x * blockDim.x + threadIdx.x;
    if (e < N_EDGES) {
        int c = edge_at(ei, (long long)N_EDGES + e);   // col (destination)
        if ((unsigned)c < N_NODES) atomicAdd(&g_deg[c], 1);
    }
}

// Phase B: per-block sums of degrees (391 blocks x 256)
__global__ void k_blocksum() {
    __shared__ int sh[256];
    int t = threadIdx.x;
    int i = blockIdx.x * 256 + t;
    int d = (i < N_NODES) ? g_deg[i] : 0;
    sh[t] = d;
    __syncthreads();
    #pragma unroll
    for (int off = 128; off > 0; off >>= 1) {
        if (t < off) sh[t] += sh[t + off];
        __syncthreads();
    }
    if (t == 0) g_bsum[blockIdx.x] = sh[0];
}

// Phase C: single small block scans the 391 block sums -> exclusive
__global__ void k_scanb() {
    __shared__ int sh[512];
    int t = threadIdx.x;
    int v = (t < NBLK) ? g_bsum[t] : 0;
    sh[t] = v;
    __syncthreads();
    #pragma unroll
    for (int off = 1; off < 512; off <<= 1) {
        int u = (t >= off) ? sh[t - off] : 0;
        __syncthreads();
        sh[t] += u;
        __syncthreads();
    }
    if (t < NBLK) g_bsum[t] = sh[t] - v;          // exclusive
    if (t == NBLK) g_bsum[NBLK] = sh[511];
}

// Phase D: intra-block exclusive scan + global offset + dinv
__global__ void k_offsets() {
    __shared__ int sh[256];
    int t = threadIdx.x;
    int i = blockIdx.x * 256 + t;
    int d = (i < N_NODES) ? g_deg[i] : 0;
    sh[t] = d;
    __syncthreads();
    #pragma unroll
    for (int off = 1; off < 256; off <<= 1) {
        int u = (t >= off) ? sh[t - off] : 0;
        __syncthreads();
        sh[t] += u;
        __syncthreads();
    }
    if (i < N_NODES) {
        g_off[i] = g_bsum[blockIdx.x] + sh[t] - d;
        g_dinv[i] = rsqrtf((float)(d + 1));
    }
    if (i == 0) g_off[N_NODES] = N_EDGES;
}

__global__ void k_fill(const void* __restrict__ ei) {
    int e = blockIdx.x * blockDim.x + threadIdx.x;
    if (e < N_EDGES) {
        int r = edge_at(ei, e);
        int c = edge_at(ei, (long long)N_EDGES + e);
        if ((unsigned)r >= N_NODES || (unsigned)c >= N_NODES) return;
        int pos = g_off[c] + atomicAdd(&g_cur[c], 1);
        if ((unsigned)pos < N_EDGES) g_src[pos] = r;
    }
}

// ---------------- GEMM: Y[n,128] = X[n,128] @ W[128,128] --------------------
// 256 threads, 128-row tile, K tiled by 32, 8x8 micro-tile, packed f32x2 FMA.
#define FFMA2(d, a, b) \
    asm("fma.rn.f32x2 %0, %1, %2, %0;" : "+l"(d) : "l"(a), "l"(b))

__global__ void __launch_bounds__(256) k_gemm(const float* __restrict__ Xext,
                                              const float* __restrict__ W,
                                              int srcSel, int dstSel) {
    __shared__ float As[128 * 32];   // [row][k] current K-slab
    __shared__ float Ws[32 * 128];   // [k][col] current K-slab

    const float* X = srcSel ? g_buf1 : Xext;
    float*       Y = dstSel ? g_buf1 : g_buf0;

    int tid = threadIdx.x;
    int rowBase = blockIdx.x * 128;

    int rg = (tid >> 4) << 3;     // row offset (0..120)
    int cg = (tid & 15) << 3;     // col offset (0..120)

    u64t acc[8][4];
    #pragma unroll
    for (int i = 0; i < 8; i++)
        #pragma unroll
        for (int j = 0; j < 4; j++) acc[i][j] = 0ull;

    const float4* Xv = (const float4*)X;
    const float4* Wv = (const float4*)W;

    #pragma unroll 1
    for (int kt = 0; kt < 4; kt++) {
        #pragma unroll
        for (int i = 0; i < 4; i++) {
            int lin = tid + 256 * i;
            int r = lin >> 3;              // 0..127
            int q = lin & 7;
            int gr = rowBase + r;
            float4 v = (gr < N_NODES) ? Xv[(size_t)gr * 32 + kt * 8 + q]
                                      : make_float4(0.f, 0.f, 0.f, 0.f);
            *(float4*)&As[r * 32 + q * 4] = v;
        }
        #pragma unroll
        for (int i = 0; i < 4; i++) {
            int lin = tid + 256 * i;
            int wr = lin >> 5;             // 0..31
            int wc = lin & 31;
            *(float4*)&Ws[wr * 128 + wc * 4] = Wv[(size_t)(kt * 32 + wr) * 32 + wc];
        }
        __syncthreads();

        #pragma unroll
        for (int kk = 0; kk < 32; kk++) {
            u64t b2[4];
            {
                ulonglong2 p0 = *(const ulonglong2*)&Ws[kk * 128 + cg];
                ulonglong2 p1 = *(const ulonglong2*)&Ws[kk * 128 + cg + 4];
                b2[0] = p0.x; b2[1] = p0.y; b2[2] = p1.x; b2[3] = p1.y;
            }
            #pragma unroll
            for (int i = 0; i < 8; i++) {
                float a = As[(rg + i) * 32 + kk];
                u64t a2;
                asm("mov.b64 %0, {%1, %1};" : "=l"(a2) : "f"(a));
                FFMA2(acc[i][0], a2, b2[0]);
                FFMA2(acc[i][1], a2, b2[1]);
                FFMA2(acc[i][2], a2, b2[2]);
                FFMA2(acc[i][3], a2, b2[3]);
            }
        }
        __syncthreads();
    }

    #pragma unroll
    for (int i = 0; i < 8; i++) {
        int r = rowBase + rg + i;
        if (r < N_NODES) {
            ulonglong2* yo = (ulonglong2*)&Y[(size_t)r * 128 + cg];
            ulonglong2 o0; o0.x = acc[i][0]; o0.y = acc[i][1];
            ulonglong2 o1; o1.x = acc[i][2]; o1.y = acc[i][3];
            yo[0] = o0; yo[1] = o1;
        }
    }
}

// ---------------- aggregation: warp-per-node CSC gather, MLP-4 --------------
// out[c] = dinv[c]^2 * xt[c] + sum_{s in in(c)} dinv[s]*dinv[c]*xt[s] + bias
__global__ void __launch_bounds__(256) k_agg(const float* __restrict__ bias,
                                             float* __restrict__ outExt,
                                             int useExtOut) {
    int gw = (blockIdx.x * blockDim.x + threadIdx.x) >> 5;
    int lane = threadIdx.x & 31;
    if (gw >= N_NODES) return;
    int c = gw;

    const float4* xv = (const float4*)g_buf0;
    float*        out = useExtOut ? outExt : g_buf1;

    float dc = g_dinv[c];
    float4 acc = xv[(size_t)c * 32 + lane];
    float sw = dc * dc;
    acc.x *= sw; acc.y *= sw; acc.z *= sw; acc.w *= sw;

    int e0 = g_off[c], e1 = g_off[c + 1];
    int e = e0;
    for (; e + 4 <= e1; e += 4) {
        int s0 = __ldg(&g_src[e]);
        int s1 = __ldg(&g_src[e + 1]);
        int s2 = __ldg(&g_src[e + 2]);
        int s3 = __ldg(&g_src[e + 3]);
        float w0 = g_dinv[s0] * dc;
        float w1 = g_dinv[s1] * dc;
        float w2 = g_dinv[s2] * dc;
        float w3 = g_dinv[s3] * dc;
        float4 v0 = xv[(size_t)s0 * 32 + lane];
        float4 v1 = xv[(size_t)s1 * 32 + lane];
        float4 v2 = xv[(size_t)s2 * 32 + lane];
        float4 v3 = xv[(size_t)s3 * 32 + lane];
        acc.x += v0.x * w0; acc.y += v0.y * w0; acc.z += v0.z * w0; acc.w += v0.w * w0;
        acc.x += v1.x * w1; acc.y += v1.y * w1; acc.z += v1.z * w1; acc.w += v1.w * w1;
        acc.x += v2.x * w2; acc.y += v2.y * w2; acc.z += v2.z * w2; acc.w += v2.w * w2;
        acc.x += v3.x * w3; acc.y += v3.y * w3; acc.z += v3.z * w3; acc.w += v3.w * w3;
    }
    for (; e < e1; e++) {
        int s = __ldg(&g_src[e]);
        float w = g_dinv[s] * dc;
        float4 v = xv[(size_t)s * 32 + lane];
        acc.x += v.x * w; acc.y += v.y * w; acc.z += v.z * w; acc.w += v.w * w;
    }

    float4 b = ((const float4*)bias)[lane];
    acc.x += b.x; acc.y += b.y; acc.z += b.z; acc.w += b.w;
    ((float4*)out)[(size_t)c * 32 + lane] = acc;
}

// ---------------- launch -----------------------------------------------------
extern "C" void kernel_launch(void* const* d_in, const int* in_sizes, int n_in,
                              void* d_out, int out_size) {
    const float* X  = (const float*)d_in[0];
    const void*  EI = d_in[1];
    const float* W1 = (const float*)d_in[2];
    const float* B1 = (const float*)d_in[3];
    const float* W2 = (const float*)d_in[4];
    const float* B2 = (const float*)d_in[5];
    float*       out = (float*)d_out;

    const int edgeBlocks = (N_EDGES + 255) / 256;
    const int gemmBlocks = (N_NODES + 127) / 128;
    const int aggBlocks  = (N_NODES * 32 + 255) / 256;

    // detect edge_index dtype, then build CSC (by destination)
    k_probe<<<1, 256>>>((const int*)EI);
    k_zero<<<NBLK, 256>>>();
    k_count<<<edgeBlocks, 256>>>(EI);
    k_blocksum<<<NBLK, 256>>>();
    k_scanb<<<1, 512>>>();
    k_offsets<<<NBLK, 256>>>();
    k_fill<<<edgeBlocks, 256>>>(EI);

    // layer 1
    k_gemm<<<gemmBlocks, 256>>>(X, W1, /*src=*/0, /*dst=*/0);   // xt -> buf0
    k_agg<<<aggBlocks, 256>>>(B1, out, /*useExtOut=*/0);        // h  -> buf1

    // layer 2
    k_gemm<<<gemmBlocks, 256>>>(nullptr, W2, /*src=*/1, /*dst=*/0); // buf1 -> buf0
    k_agg<<<aggBlocks, 256>>>(B2, out, /*useExtOut=*/1);            // -> d_out
}